// round 2
// baseline (speedup 1.0000x reference)
#include <cuda_runtime.h>
#include <cstdint>
#include <math.h>

#define T_SEQ 4096
#define B_BATCH 4
#define DM 1024
#define HS 128

// scratch for q,k,v projections: [B*T, 128] each (static device arrays, no allocs)
__device__ float g_q[B_BATCH * T_SEQ * HS];
__device__ float g_k[B_BATCH * T_SEQ * HS];
__device__ float g_v[B_BATCH * T_SEQ * HS];

__device__ __forceinline__ uint32_t tf32r(float x) {
    uint32_t u;
    asm("cvt.rna.tf32.f32 %0, %1;" : "=r"(u) : "f"(x));
    return u;
}

__device__ __forceinline__ void mma_tf32(float c[4],
                                         uint32_t a0, uint32_t a1, uint32_t a2, uint32_t a3,
                                         uint32_t b0, uint32_t b1) {
    asm volatile(
        "mma.sync.aligned.m16n8k8.row.col.f32.tf32.tf32.f32 "
        "{%0,%1,%2,%3},{%4,%5,%6,%7},{%8,%9},{%0,%1,%2,%3};\n"
        : "+f"(c[0]), "+f"(c[1]), "+f"(c[2]), "+f"(c[3])
        : "r"(a0), "r"(a1), "r"(a2), "r"(a3), "r"(b0), "r"(b1));
}

// ---------------------------------------------------------------------------
// Projection: out[m, n] = sum_k x[m, k] * W[n, k]
// M = B*T = 16384 (128-row tiles), N = 128, K = 1024 (32-chunks)
// blockIdx.x = m-tile, blockIdx.y = which of {Wq, Wk, Wv}
// ---------------------------------------------------------------------------
__global__ __launch_bounds__(256) void proj_kernel(const float* __restrict__ x,
                                                   const float* __restrict__ Wq,
                                                   const float* __restrict__ Wk,
                                                   const float* __restrict__ Wv) {
    __shared__ float Xs[128 * 36];  // [m][k], stride 36 (4 mod 32 -> conflict-free frag loads)
    __shared__ float Ws[128 * 36];  // [n][k]

    const int which = blockIdx.y;
    const float* W = (which == 0) ? Wq : (which == 1) ? Wk : Wv;
    float* outp = (which == 0) ? g_q : (which == 1) ? g_k : g_v;

    const int mbase = blockIdx.x * 128;
    const int tid = threadIdx.x;
    const int warp = tid >> 5, lane = tid & 31;
    const int gid = lane >> 2, tig = lane & 3;
    const int warpM = warp >> 1;  // 0..3 -> 32 rows each
    const int warpN = warp & 1;   // 0..1 -> 64 cols each

    float acc[2][8][4];
#pragma unroll
    for (int mi = 0; mi < 2; mi++)
#pragma unroll
        for (int ni = 0; ni < 8; ni++)
#pragma unroll
            for (int j = 0; j < 4; j++) acc[mi][ni][j] = 0.f;

    for (int k0 = 0; k0 < DM; k0 += 32) {
#pragma unroll
        for (int i = 0; i < 4; i++) {
            int idx = tid + i * 256;     // 0..1023
            int row = idx >> 3;          // 0..127
            int c4 = idx & 7;            // float4 index in 32-wide chunk
            float4 xv = *(const float4*)(x + (size_t)(mbase + row) * DM + k0 + c4 * 4);
            float* d = &Xs[row * 36 + c4 * 4];
            d[0] = __uint_as_float(tf32r(xv.x));
            d[1] = __uint_as_float(tf32r(xv.y));
            d[2] = __uint_as_float(tf32r(xv.z));
            d[3] = __uint_as_float(tf32r(xv.w));
            float4 wv = *(const float4*)(W + (size_t)row * DM + k0 + c4 * 4);
            float* dw = &Ws[row * 36 + c4 * 4];
            dw[0] = __uint_as_float(tf32r(wv.x));
            dw[1] = __uint_as_float(tf32r(wv.y));
            dw[2] = __uint_as_float(tf32r(wv.z));
            dw[3] = __uint_as_float(tf32r(wv.w));
        }
        __syncthreads();

#pragma unroll
        for (int kk = 0; kk < 4; kk++) {
            const int kb = kk * 8;
            uint32_t a[2][4];
#pragma unroll
            for (int mi = 0; mi < 2; mi++) {
                int r = warpM * 32 + mi * 16 + gid;
                a[mi][0] = __float_as_uint(Xs[r * 36 + kb + tig]);
                a[mi][1] = __float_as_uint(Xs[(r + 8) * 36 + kb + tig]);
                a[mi][2] = __float_as_uint(Xs[r * 36 + kb + tig + 4]);
                a[mi][3] = __float_as_uint(Xs[(r + 8) * 36 + kb + tig + 4]);
            }
            uint32_t bb[8][2];
#pragma unroll
            for (int ni = 0; ni < 8; ni++) {
                int n = warpN * 64 + ni * 8 + gid;
                bb[ni][0] = __float_as_uint(Ws[n * 36 + kb + tig]);
                bb[ni][1] = __float_as_uint(Ws[n * 36 + kb + tig + 4]);
            }
#pragma unroll
            for (int mi = 0; mi < 2; mi++)
#pragma unroll
                for (int ni = 0; ni < 8; ni++)
                    mma_tf32(acc[mi][ni], a[mi][0], a[mi][1], a[mi][2], a[mi][3],
                             bb[ni][0], bb[ni][1]);
        }
        __syncthreads();
    }

#pragma unroll
    for (int mi = 0; mi < 2; mi++) {
#pragma unroll
        for (int ni = 0; ni < 8; ni++) {
            int r0 = mbase + warpM * 32 + mi * 16 + gid;
            int c0 = warpN * 64 + ni * 8 + tig * 2;
            outp[(size_t)r0 * HS + c0] = acc[mi][ni][0];
            outp[(size_t)r0 * HS + c0 + 1] = acc[mi][ni][1];
            outp[(size_t)(r0 + 8) * HS + c0] = acc[mi][ni][2];
            outp[(size_t)(r0 + 8) * HS + c0 + 1] = acc[mi][ni][3];
        }
    }
}

// ---------------------------------------------------------------------------
// Flash attention (causal): Br = Bs = 64, head = 128.
// grid = (64 q-tiles [reversed for longest-first], 4 batches), 256 threads.
// ---------------------------------------------------------------------------
#define QS_STRIDE 132  // 4 mod 32
#define VS_STRIDE 68   // 4 mod 32
#define PS_STRIDE 68

__global__ __launch_bounds__(256) void flash_kernel(float* __restrict__ out) {
    extern __shared__ float sm[];
    float* Qs = sm;                       // 64 * 132
    float* Ks = Qs + 64 * QS_STRIDE;      // 64 * 132
    float* Vs = Ks + 64 * QS_STRIDE;      // 128 * 68 (transposed: [head][s])
    float* Ps = Vs + 128 * VS_STRIDE;     // 64 * 68
    float* m_i = Ps + 64 * PS_STRIDE;     // 64
    float* l_i = m_i + 64;                // 64
    float* rsc = l_i + 64;                // 64

    const int b = blockIdx.y;
    const int qt = (gridDim.x - 1) - blockIdx.x;  // longest blocks first
    const int qbase = qt * 64;

    const int tid = threadIdx.x;
    const int warp = tid >> 5, lane = tid & 31;
    const int gid = lane >> 2, tig = lane & 3;
    const int warpM = warp >> 1;  // 0..3 -> 16 q-rows each
    const int warpN = warp & 1;   // 0..1

    // load Q tile (tf32-rounded)
    for (int idx = tid; idx < 64 * 128; idx += 256) {
        int r = idx >> 7, h = idx & 127;
        Qs[r * QS_STRIDE + h] =
            __uint_as_float(tf32r(g_q[((size_t)b * T_SEQ + qbase + r) * HS + h]));
    }
    if (tid < 64) {
        m_i[tid] = -INFINITY;
        l_i[tid] = 0.f;
    }

    float o[8][4];
#pragma unroll
    for (int ni = 0; ni < 8; ni++)
#pragma unroll
        for (int j = 0; j < 4; j++) o[ni][j] = 0.f;

    const float invs = 0.08838834764831845f;  // 1/sqrt(128)
    const int r0 = warpM * 16 + gid;

    for (int kt = 0; kt <= qt; kt++) {
        const int kbase = kt * 64;
        __syncthreads();  // previous tile fully consumed (also guards Q load / stats init)

        for (int idx = tid; idx < 64 * 128; idx += 256) {
            int s = idx >> 7, h = idx & 127;
            size_t gi = ((size_t)b * T_SEQ + kbase + s) * HS + h;
            Ks[s * QS_STRIDE + h] = __uint_as_float(tf32r(g_k[gi]));
            Vs[h * VS_STRIDE + s] = __uint_as_float(tf32r(g_v[gi]));
        }
        __syncthreads();

        // S = Q Kᵀ (64x64, k=128)
        float sacc[4][4];
#pragma unroll
        for (int ni = 0; ni < 4; ni++)
#pragma unroll
            for (int j = 0; j < 4; j++) sacc[ni][j] = 0.f;

#pragma unroll
        for (int kk = 0; kk < 16; kk++) {
            const int kb = kk * 8;
            uint32_t a0 = __float_as_uint(Qs[r0 * QS_STRIDE + kb + tig]);
            uint32_t a1 = __float_as_uint(Qs[(r0 + 8) * QS_STRIDE + kb + tig]);
            uint32_t a2 = __float_as_uint(Qs[r0 * QS_STRIDE + kb + tig + 4]);
            uint32_t a3 = __float_as_uint(Qs[(r0 + 8) * QS_STRIDE + kb + tig + 4]);
#pragma unroll
            for (int ni = 0; ni < 4; ni++) {
                int n = warpN * 32 + ni * 8 + gid;
                uint32_t b0 = __float_as_uint(Ks[n * QS_STRIDE + kb + tig]);
                uint32_t b1 = __float_as_uint(Ks[n * QS_STRIDE + kb + tig + 4]);
                mma_tf32(sacc[ni], a0, a1, a2, a3, b0, b1);
            }
        }

        // spill S to smem with scale + causal mask
        const bool diag = (kt == qt);
#pragma unroll
        for (int ni = 0; ni < 4; ni++) {
            int c0 = warpN * 32 + ni * 8 + tig * 2;
            float v0 = sacc[ni][0] * invs;
            float v1 = sacc[ni][1] * invs;
            float v2 = sacc[ni][2] * invs;
            float v3 = sacc[ni][3] * invs;
            if (diag) {
                if (c0 > r0) v0 = -1e30f;
                if (c0 + 1 > r0) v1 = -1e30f;
                if (c0 > r0 + 8) v2 = -1e30f;
                if (c0 + 1 > r0 + 8) v3 = -1e30f;
            }
            Ps[r0 * PS_STRIDE + c0] = v0;
            Ps[r0 * PS_STRIDE + c0 + 1] = v1;
            Ps[(r0 + 8) * PS_STRIDE + c0] = v2;
            Ps[(r0 + 8) * PS_STRIDE + c0 + 1] = v3;
        }
        __syncthreads();

        // online softmax: 4 threads per row (row = tid>>2), quad shfl reduction.
        // Quads (lanes 4k..4k+3) never cross a warp boundary -> shfl_xor 1,2 valid.
        {
            const int r = tid >> 2;
            const int qq = tid & 3;
            float* prow = &Ps[r * PS_STRIDE + qq * 16];
            float mold = m_i[r];
            float mx = -INFINITY;
#pragma unroll
            for (int c = 0; c < 16; c++) mx = fmaxf(mx, prow[c]);
            mx = fmaxf(mx, __shfl_xor_sync(0xffffffffu, mx, 1));
            mx = fmaxf(mx, __shfl_xor_sync(0xffffffffu, mx, 2));
            mx = fmaxf(mx, mold);
            float lsum = 0.f;
#pragma unroll
            for (int c = 0; c < 16; c++) {
                float p = __expf(prow[c] - mx);
                lsum += p;
                prow[c] = __uint_as_float(tf32r(p));
            }
            lsum += __shfl_xor_sync(0xffffffffu, lsum, 1);
            lsum += __shfl_xor_sync(0xffffffffu, lsum, 2);
            if (qq == 0) {
                float sc = __expf(mold - mx);
                m_i[r] = mx;
                l_i[r] = l_i[r] * sc + lsum;
                rsc[r] = sc;
            }
        }
        __syncthreads();

        // rescale O, then O += P @ V
        {
            float s0 = rsc[r0], s1 = rsc[r0 + 8];
#pragma unroll
            for (int ni = 0; ni < 8; ni++) {
                o[ni][0] *= s0;
                o[ni][1] *= s0;
                o[ni][2] *= s1;
                o[ni][3] *= s1;
            }
#pragma unroll
            for (int kk = 0; kk < 8; kk++) {
                const int kb = kk * 8;
                uint32_t a0 = __float_as_uint(Ps[r0 * PS_STRIDE + kb + tig]);
                uint32_t a1 = __float_as_uint(Ps[(r0 + 8) * PS_STRIDE + kb + tig]);
                uint32_t a2 = __float_as_uint(Ps[r0 * PS_STRIDE + kb + tig + 4]);
                uint32_t a3 = __float_as_uint(Ps[(r0 + 8) * PS_STRIDE + kb + tig + 4]);
#pragma unroll
                for (int ni = 0; ni < 8; ni++) {
                    int n = warpN * 64 + ni * 8 + gid;
                    uint32_t b0 = __float_as_uint(Vs[n * VS_STRIDE + kb + tig]);
                    uint32_t b1 = __float_as_uint(Vs[n * VS_STRIDE + kb + tig + 4]);
                    mma_tf32(o[ni], a0, a1, a2, a3, b0, b1);
                }
            }
        }
    }

    // normalize and write out (l_i final: written before last pre-PV sync)
    float li0 = 1.f / l_i[r0];
    float li1 = 1.f / l_i[r0 + 8];
#pragma unroll
    for (int ni = 0; ni < 8; ni++) {
        int c0 = warpN * 64 + ni * 8 + tig * 2;
        size_t base0 = ((size_t)b * T_SEQ + qbase + r0) * HS;
        size_t base1 = ((size_t)b * T_SEQ + qbase + r0 + 8) * HS;
        out[base0 + c0] = o[ni][0] * li0;
        out[base0 + c0 + 1] = o[ni][1] * li0;
        out[base1 + c0] = o[ni][2] * li1;
        out[base1 + c0 + 1] = o[ni][3] * li1;
    }
}

extern "C" void kernel_launch(void* const* d_in, const int* in_sizes, int n_in,
                              void* d_out, int out_size) {
    const float* x = (const float*)d_in[0];
    const float* Wq = (const float*)d_in[1];
    const float* Wk = (const float*)d_in[2];
    const float* Wv = (const float*)d_in[3];
    float* out = (float*)d_out;

    // projections: q,k,v = x @ W^T into device scratch
    proj_kernel<<<dim3(128, 3), 256>>>(x, Wq, Wk, Wv);

    // flash attention
    const int smem_bytes = (64 * QS_STRIDE + 64 * QS_STRIDE + 128 * VS_STRIDE +
                            64 * PS_STRIDE + 3 * 64) *
                           (int)sizeof(float);
    cudaFuncSetAttribute(flash_kernel, cudaFuncAttributeMaxDynamicSharedMemorySize,
                         smem_bytes);
    flash_kernel<<<dim3(64, B_BATCH), 256, smem_bytes>>>(out);
}

// round 3
// speedup vs baseline: 1.5121x; 1.5121x over previous
#include <cuda_runtime.h>
#include <cstdint>
#include <math.h>

#define T_SEQ 4096
#define B_BATCH 4
#define DM 1024
#define HS 128
#define BT_TOT (B_BATCH * T_SEQ)

// scratch: q,k row-major [B*T,128]; v transposed [128][B*T]; all tf32-pre-rounded
__device__ float g_q[BT_TOT * HS];
__device__ float g_k[BT_TOT * HS];
__device__ float g_vT[HS * BT_TOT];

__device__ __forceinline__ uint32_t tf32r(float x) {
    uint32_t u;
    asm("cvt.rna.tf32.f32 %0, %1;" : "=r"(u) : "f"(x));
    return u;
}

__device__ __forceinline__ void mma_tf32(float c[4],
                                         uint32_t a0, uint32_t a1, uint32_t a2, uint32_t a3,
                                         uint32_t b0, uint32_t b1) {
    asm volatile(
        "mma.sync.aligned.m16n8k8.row.col.f32.tf32.tf32.f32 "
        "{%0,%1,%2,%3},{%4,%5,%6,%7},{%8,%9},{%0,%1,%2,%3};\n"
        : "+f"(c[0]), "+f"(c[1]), "+f"(c[2]), "+f"(c[3])
        : "r"(a0), "r"(a1), "r"(a2), "r"(a3), "r"(b0), "r"(b1));
}

__device__ __forceinline__ void cpa16(uint32_t dst, const float* src) {
    asm volatile("cp.async.cg.shared.global [%0], [%1], 16;\n" ::"r"(dst), "l"(src));
}
__device__ __forceinline__ void cpa_commit() { asm volatile("cp.async.commit_group;\n"); }
__device__ __forceinline__ void cpa_wait0() { asm volatile("cp.async.wait_group 0;\n"); }

// ---------------------------------------------------------------------------
// Projection: q,k,v = x @ W^T ; q,k stored row-major tf32; v stored transposed tf32
// ---------------------------------------------------------------------------
__global__ __launch_bounds__(256) void proj_kernel(const float* __restrict__ x,
                                                   const float* __restrict__ Wq,
                                                   const float* __restrict__ Wk,
                                                   const float* __restrict__ Wv) {
    __shared__ float Xs[128 * 36];
    __shared__ float Ws[128 * 36];

    const int which = blockIdx.y;
    const float* W = (which == 0) ? Wq : (which == 1) ? Wk : Wv;

    const int mbase = blockIdx.x * 128;
    const int tid = threadIdx.x;
    const int warp = tid >> 5, lane = tid & 31;
    const int gid = lane >> 2, tig = lane & 3;
    const int warpM = warp >> 1;
    const int warpN = warp & 1;

    float acc[2][8][4];
#pragma unroll
    for (int mi = 0; mi < 2; mi++)
#pragma unroll
        for (int ni = 0; ni < 8; ni++)
#pragma unroll
            for (int j = 0; j < 4; j++) acc[mi][ni][j] = 0.f;

    for (int k0 = 0; k0 < DM; k0 += 32) {
#pragma unroll
        for (int i = 0; i < 4; i++) {
            int idx = tid + i * 256;
            int row = idx >> 3;
            int c4 = idx & 7;
            float4 xv = *(const float4*)(x + (size_t)(mbase + row) * DM + k0 + c4 * 4);
            float* d = &Xs[row * 36 + c4 * 4];
            d[0] = __uint_as_float(tf32r(xv.x));
            d[1] = __uint_as_float(tf32r(xv.y));
            d[2] = __uint_as_float(tf32r(xv.z));
            d[3] = __uint_as_float(tf32r(xv.w));
            float4 wv = *(const float4*)(W + (size_t)row * DM + k0 + c4 * 4);
            float* dw = &Ws[row * 36 + c4 * 4];
            dw[0] = __uint_as_float(tf32r(wv.x));
            dw[1] = __uint_as_float(tf32r(wv.y));
            dw[2] = __uint_as_float(tf32r(wv.z));
            dw[3] = __uint_as_float(tf32r(wv.w));
        }
        __syncthreads();

#pragma unroll
        for (int kk = 0; kk < 4; kk++) {
            const int kb = kk * 8;
            uint32_t a[2][4];
#pragma unroll
            for (int mi = 0; mi < 2; mi++) {
                int r = warpM * 32 + mi * 16 + gid;
                a[mi][0] = __float_as_uint(Xs[r * 36 + kb + tig]);
                a[mi][1] = __float_as_uint(Xs[(r + 8) * 36 + kb + tig]);
                a[mi][2] = __float_as_uint(Xs[r * 36 + kb + tig + 4]);
                a[mi][3] = __float_as_uint(Xs[(r + 8) * 36 + kb + tig + 4]);
            }
            uint32_t bb[8][2];
#pragma unroll
            for (int ni = 0; ni < 8; ni++) {
                int n = warpN * 64 + ni * 8 + gid;
                bb[ni][0] = __float_as_uint(Ws[n * 36 + kb + tig]);
                bb[ni][1] = __float_as_uint(Ws[n * 36 + kb + tig + 4]);
            }
#pragma unroll
            for (int mi = 0; mi < 2; mi++)
#pragma unroll
                for (int ni = 0; ni < 8; ni++)
                    mma_tf32(acc[mi][ni], a[mi][0], a[mi][1], a[mi][2], a[mi][3],
                             bb[ni][0], bb[ni][1]);
        }
        __syncthreads();
    }

    if (which < 2) {
        float* outp = (which == 0) ? g_q : g_k;
#pragma unroll
        for (int mi = 0; mi < 2; mi++)
#pragma unroll
            for (int ni = 0; ni < 8; ni++) {
                int r0 = mbase + warpM * 32 + mi * 16 + gid;
                int c0 = warpN * 64 + ni * 8 + tig * 2;
                outp[(size_t)r0 * HS + c0] = __uint_as_float(tf32r(acc[mi][ni][0]));
                outp[(size_t)r0 * HS + c0 + 1] = __uint_as_float(tf32r(acc[mi][ni][1]));
                outp[(size_t)(r0 + 8) * HS + c0] = __uint_as_float(tf32r(acc[mi][ni][2]));
                outp[(size_t)(r0 + 8) * HS + c0 + 1] = __uint_as_float(tf32r(acc[mi][ni][3]));
            }
    } else {
        // transposed: g_vT[h][row]
#pragma unroll
        for (int mi = 0; mi < 2; mi++)
#pragma unroll
            for (int ni = 0; ni < 8; ni++) {
                int r0 = mbase + warpM * 32 + mi * 16 + gid;
                int c0 = warpN * 64 + ni * 8 + tig * 2;
                g_vT[(size_t)c0 * BT_TOT + r0] = __uint_as_float(tf32r(acc[mi][ni][0]));
                g_vT[(size_t)(c0 + 1) * BT_TOT + r0] = __uint_as_float(tf32r(acc[mi][ni][1]));
                g_vT[(size_t)c0 * BT_TOT + r0 + 8] = __uint_as_float(tf32r(acc[mi][ni][2]));
                g_vT[(size_t)(c0 + 1) * BT_TOT + r0 + 8] = __uint_as_float(tf32r(acc[mi][ni][3]));
            }
    }
}

// ---------------------------------------------------------------------------
// Flash attention, Br=128 Bs=64, 8 warps, warp owns 16 full rows.
// K smem: [64][132] (x2 buffers), V smem: [128][68] (x2), P: per-warp [16][68].
// ---------------------------------------------------------------------------
#define KS_STRIDE 132
#define VS_STRIDE 68
#define PS_STRIDE 68
#define KBUF_FL (64 * KS_STRIDE)        // 8448 floats
#define VBUF_FL (128 * VS_STRIDE)       // 8704 floats
#define VS_OFF_FL (2 * KBUF_FL)         // 16896
#define PS_OFF_FL (VS_OFF_FL + 2 * VBUF_FL)  // 34304
#define SMEM_FL (PS_OFF_FL + 8 * 16 * PS_STRIDE)  // 43008 floats = 168KB

__device__ __forceinline__ void load_tile(uint32_t sbase, int buf, int bT, int kbase,
                                          int tid) {
    // K tile: 64 rows x 128 cols -> 2048 16B chunks
    uint32_t kdst = sbase + buf * (KBUF_FL * 4);
    const float* ksrc = g_k + (size_t)(bT + kbase) * HS;
#pragma unroll
    for (int j = 0; j < 8; j++) {
        int idx = tid + j * 256;
        int row = idx >> 5, c = idx & 31;
        cpa16(kdst + row * (KS_STRIDE * 4) + c * 16, ksrc + row * HS + c * 4);
    }
    // V tile (transposed source): 128 rows(h) x 64 cols(s) -> 2048 chunks
    uint32_t vdst = sbase + (VS_OFF_FL + buf * VBUF_FL) * 4;
    const float* vsrc = g_vT + bT + kbase;
#pragma unroll
    for (int j = 0; j < 8; j++) {
        int idx = tid + j * 256;
        int h = idx >> 4, c = idx & 15;
        cpa16(vdst + h * (VS_STRIDE * 4) + c * 16, vsrc + (size_t)h * BT_TOT + c * 4);
    }
}

__global__ __launch_bounds__(256, 1) void flash_kernel(float* __restrict__ out) {
    extern __shared__ float sm[];
    const int tid = threadIdx.x;
    const int warp = tid >> 5, lane = tid & 31;
    const int gid = lane >> 2, tig = lane & 3;
    const int b = blockIdx.y;
    const int qt = (gridDim.x - 1) - blockIdx.x;  // longest first
    const int qbase = qt * 128;
    const int wrow = warp * 16;
    const int ktmax = 2 * qt + 1;
    const int bT = b * T_SEQ;

    float* Ks = sm;
    float* Vs = sm + VS_OFF_FL;
    float* Ps = sm + PS_OFF_FL + warp * (16 * PS_STRIDE);
    uint32_t sbase = (uint32_t)__cvta_generic_to_shared(sm);

    // Q fragments in registers (pre-rounded tf32 in global)
    uint32_t q[16][4];
    {
        const float* Q0 = g_q + (size_t)(bT + qbase + wrow + gid) * HS;
        const float* Q1 = Q0 + 8 * HS;
#pragma unroll
        for (int kk = 0; kk < 16; kk++) {
            q[kk][0] = __float_as_uint(Q0[kk * 8 + tig]);
            q[kk][1] = __float_as_uint(Q1[kk * 8 + tig]);
            q[kk][2] = __float_as_uint(Q0[kk * 8 + tig + 4]);
            q[kk][3] = __float_as_uint(Q1[kk * 8 + tig + 4]);
        }
    }

    load_tile(sbase, 0, bT, 0, tid);
    cpa_commit();

    float o[16][4];
#pragma unroll
    for (int ni = 0; ni < 16; ni++)
#pragma unroll
        for (int j = 0; j < 4; j++) o[ni][j] = 0.f;
    float m0 = -1e30f, m1 = -1e30f, l0 = 0.f, l1 = 0.f;

    const float invs = 0.08838834764831845f;  // 1/sqrt(128)
    const int grow0 = qbase + wrow + gid;
    const int grow1 = grow0 + 8;

    for (int kt = 0; kt <= ktmax; kt++) {
        const int cur = kt & 1;
        cpa_wait0();
        __syncthreads();
        if (kt < ktmax) {
            load_tile(sbase, cur ^ 1, bT, (kt + 1) * 64, tid);
        }
        cpa_commit();

        const float* Kc = Ks + cur * KBUF_FL;
        const float* Vc = Vs + cur * VBUF_FL;

        // S = Q K^T : 128 rows x 64 cols, warp computes its 16 rows
        float s[8][4];
#pragma unroll
        for (int ni = 0; ni < 8; ni++)
#pragma unroll
            for (int j = 0; j < 4; j++) s[ni][j] = 0.f;

#pragma unroll
        for (int kk = 0; kk < 16; kk++) {
            const int kb = kk * 8;
#pragma unroll
            for (int ni = 0; ni < 8; ni++) {
                const float* kp = Kc + (ni * 8 + gid) * KS_STRIDE + kb + tig;
                uint32_t b0 = __float_as_uint(kp[0]);
                uint32_t b1 = __float_as_uint(kp[4]);
                mma_tf32(s[ni], q[kk][0], q[kk][1], q[kk][2], q[kk][3], b0, b1);
            }
        }

        // scale + causal mask (only last two k-tiles can mask)
        const int kbase = kt * 64;
        const bool dm = (kt >= 2 * qt);
#pragma unroll
        for (int ni = 0; ni < 8; ni++) {
            int c0 = kbase + ni * 8 + tig * 2;
            float v0 = s[ni][0] * invs;
            float v1 = s[ni][1] * invs;
            float v2 = s[ni][2] * invs;
            float v3 = s[ni][3] * invs;
            if (dm) {
                if (c0 > grow0) v0 = -1e30f;
                if (c0 + 1 > grow0) v1 = -1e30f;
                if (c0 > grow1) v2 = -1e30f;
                if (c0 + 1 > grow1) v3 = -1e30f;
            }
            s[ni][0] = v0;
            s[ni][1] = v1;
            s[ni][2] = v2;
            s[ni][3] = v3;
        }

        // warp-local online softmax (rows gid, gid+8; quad reduction)
        float mx0 = -1e30f, mx1 = -1e30f;
#pragma unroll
        for (int ni = 0; ni < 8; ni++) {
            mx0 = fmaxf(mx0, fmaxf(s[ni][0], s[ni][1]));
            mx1 = fmaxf(mx1, fmaxf(s[ni][2], s[ni][3]));
        }
        mx0 = fmaxf(mx0, __shfl_xor_sync(0xffffffffu, mx0, 1));
        mx0 = fmaxf(mx0, __shfl_xor_sync(0xffffffffu, mx0, 2));
        mx1 = fmaxf(mx1, __shfl_xor_sync(0xffffffffu, mx1, 1));
        mx1 = fmaxf(mx1, __shfl_xor_sync(0xffffffffu, mx1, 2));
        float nm0 = fmaxf(m0, mx0), nm1 = fmaxf(m1, mx1);
        float sc0 = __expf(m0 - nm0), sc1 = __expf(m1 - nm1);
        m0 = nm0;
        m1 = nm1;
        float sum0 = 0.f, sum1 = 0.f;
#pragma unroll
        for (int ni = 0; ni < 8; ni++) {
            float p0 = __expf(s[ni][0] - m0);
            float p1 = __expf(s[ni][1] - m0);
            float p2 = __expf(s[ni][2] - m1);
            float p3 = __expf(s[ni][3] - m1);
            sum0 += p0 + p1;
            sum1 += p2 + p3;
            s[ni][0] = __uint_as_float(tf32r(p0));
            s[ni][1] = __uint_as_float(tf32r(p1));
            s[ni][2] = __uint_as_float(tf32r(p2));
            s[ni][3] = __uint_as_float(tf32r(p3));
        }
        sum0 += __shfl_xor_sync(0xffffffffu, sum0, 1);
        sum0 += __shfl_xor_sync(0xffffffffu, sum0, 2);
        sum1 += __shfl_xor_sync(0xffffffffu, sum1, 1);
        sum1 += __shfl_xor_sync(0xffffffffu, sum1, 2);
        l0 = l0 * sc0 + sum0;
        l1 = l1 * sc1 + sum1;

        // rescale O
#pragma unroll
        for (int ni = 0; ni < 16; ni++) {
            o[ni][0] *= sc0;
            o[ni][1] *= sc0;
            o[ni][2] *= sc1;
            o[ni][3] *= sc1;
        }

        // spill P to warp-private smem (A-layout round trip)
#pragma unroll
        for (int ni = 0; ni < 8; ni++) {
            *(float2*)&Ps[gid * PS_STRIDE + ni * 8 + tig * 2] =
                make_float2(s[ni][0], s[ni][1]);
            *(float2*)&Ps[(gid + 8) * PS_STRIDE + ni * 8 + tig * 2] =
                make_float2(s[ni][2], s[ni][3]);
        }
        __syncwarp();

        // O += P @ V  (V smem is [head][s] = B col-major)
#pragma unroll
        for (int kk = 0; kk < 8; kk++) {
            const int kb = kk * 8;
            uint32_t a0 = __float_as_uint(Ps[gid * PS_STRIDE + kb + tig]);
            uint32_t a1 = __float_as_uint(Ps[(gid + 8) * PS_STRIDE + kb + tig]);
            uint32_t a2 = __float_as_uint(Ps[gid * PS_STRIDE + kb + tig + 4]);
            uint32_t a3 = __float_as_uint(Ps[(gid + 8) * PS_STRIDE + kb + tig + 4]);
#pragma unroll
            for (int ni = 0; ni < 16; ni++) {
                const float* vp = Vc + (ni * 8 + gid) * VS_STRIDE + kb + tig;
                uint32_t b0 = __float_as_uint(vp[0]);
                uint32_t b1 = __float_as_uint(vp[4]);
                mma_tf32(o[ni], a0, a1, a2, a3, b0, b1);
            }
        }
        __syncwarp();
    }

    // epilogue
    float il0 = 1.f / l0, il1 = 1.f / l1;
    float* out0 = out + (size_t)(bT + grow0) * HS;
    float* out1 = out + (size_t)(bT + grow1) * HS;
#pragma unroll
    for (int ni = 0; ni < 16; ni++) {
        int c0 = ni * 8 + tig * 2;
        *(float2*)&out0[c0] = make_float2(o[ni][0] * il0, o[ni][1] * il0);
        *(float2*)&out1[c0] = make_float2(o[ni][2] * il1, o[ni][3] * il1);
    }
}

extern "C" void kernel_launch(void* const* d_in, const int* in_sizes, int n_in,
                              void* d_out, int out_size) {
    const float* x = (const float*)d_in[0];
    const float* Wq = (const float*)d_in[1];
    const float* Wk = (const float*)d_in[2];
    const float* Wv = (const float*)d_in[3];
    float* out = (float*)d_out;

    proj_kernel<<<dim3(128, 3), 256>>>(x, Wq, Wk, Wv);

    const int smem_bytes = SMEM_FL * (int)sizeof(float);  // 172032
    cudaFuncSetAttribute(flash_kernel, cudaFuncAttributeMaxDynamicSharedMemorySize,
                         smem_bytes);
    flash_kernel<<<dim3(32, B_BATCH), 256, smem_bytes>>>(out);
}

// round 7
// speedup vs baseline: 2.8388x; 1.8773x over previous
#include <cuda_runtime.h>
#include <cuda_fp16.h>
#include <cstdint>

#define T_SEQ 4096
#define B_BATCH 4
#define DM 1024
#define HS 128
#define BT_TOT (B_BATCH * T_SEQ)

// fp16 scratch (static device arrays; no allocations)
__device__ __half g_xh[BT_TOT * DM];        // x converted to fp16
__device__ __half g_wh[3 * HS * DM];        // Wq,Wk,Wv converted to fp16
__device__ __half g_qh[BT_TOT * HS];
__device__ __half g_kh[BT_TOT * HS];
__device__ __half g_vTh[HS * BT_TOT];       // V transposed [h][b*T+t]

__device__ __forceinline__ void mma_f16(float c[4],
                                        uint32_t a0, uint32_t a1, uint32_t a2, uint32_t a3,
                                        uint32_t b0, uint32_t b1) {
    asm volatile(
        "mma.sync.aligned.m16n8k16.row.col.f32.f16.f16.f32 "
        "{%0,%1,%2,%3},{%4,%5,%6,%7},{%8,%9},{%0,%1,%2,%3};\n"
        : "+f"(c[0]), "+f"(c[1]), "+f"(c[2]), "+f"(c[3])
        : "r"(a0), "r"(a1), "r"(a2), "r"(a3), "r"(b0), "r"(b1));
}

__device__ __forceinline__ void cpa16(uint32_t dst, const __half* src) {
    asm volatile("cp.async.cg.shared.global [%0], [%1], 16;\n" ::"r"(dst), "l"(src));
}
__device__ __forceinline__ void cpa_commit() { asm volatile("cp.async.commit_group;\n"); }
__device__ __forceinline__ void cpa_wait0() { asm volatile("cp.async.wait_group 0;\n"); }

__device__ __forceinline__ uint32_t h2u(__half2 h) {
    return *reinterpret_cast<uint32_t*>(&h);
}

// ---------------------------------------------------------------------------
// fp32 -> fp16 conversion (8 elems / thread)
// ---------------------------------------------------------------------------
__global__ __launch_bounds__(256) void cvt_kernel(const float* __restrict__ src,
                                                  __half* __restrict__ dst, int n) {
    int i = (blockIdx.x * 256 + threadIdx.x) * 8;
    if (i >= n) return;
    float4 a = *(const float4*)(src + i);
    float4 b = *(const float4*)(src + i + 4);
    uint4 o;
    o.x = h2u(__float22half2_rn(make_float2(a.x, a.y)));
    o.y = h2u(__float22half2_rn(make_float2(a.z, a.w)));
    o.z = h2u(__float22half2_rn(make_float2(b.x, b.y)));
    o.w = h2u(__float22half2_rn(make_float2(b.z, b.w)));
    *(uint4*)(dst + i) = o;
}

// ---------------------------------------------------------------------------
// Projection (fp16): out[m,n] = sum_k xh[m,k] * wh[n,k]
// 128-row m-tiles, N=128, K=1024 in 64-chunks, cp.async double-buffered.
// smem rows padded to 72 halves (36 words; 36 mod 32 = 4 -> conflict-free).
// ---------------------------------------------------------------------------
#define PJ_STRIDE 72
#define PJ_BUF (128 * PJ_STRIDE)  // halves

__global__ __launch_bounds__(256) void proj_kernel() {
    extern __shared__ __half smh[];
    __half* X[2] = {smh, smh + PJ_BUF};
    __half* W[2] = {smh + 2 * PJ_BUF, smh + 3 * PJ_BUF};
    uint32_t sbase = (uint32_t)__cvta_generic_to_shared(smh);

    const int which = blockIdx.y;
    const __half* wsrc = g_wh + (size_t)which * HS * DM;
    const int mbase = blockIdx.x * 128;
    const int tid = threadIdx.x;
    const int warp = tid >> 5, lane = tid & 31;
    const int gid = lane >> 2, tig = lane & 3;
    const int warpM = warp >> 1;
    const int warpN = warp & 1;

    auto load_chunk = [&](int buf, int k0) {
#pragma unroll
        for (int j = 0; j < 4; j++) {
            int idx = tid + j * 256;
            int row = idx >> 3, c = idx & 7;
            cpa16(sbase + buf * (PJ_BUF * 2) + row * (PJ_STRIDE * 2) + c * 16,
                  g_xh + (size_t)(mbase + row) * DM + k0 + c * 8);
            cpa16(sbase + (2 + buf) * (PJ_BUF * 2) + row * (PJ_STRIDE * 2) + c * 16,
                  wsrc + (size_t)row * DM + k0 + c * 8);
        }
    };

    float acc[2][8][4];
#pragma unroll
    for (int mi = 0; mi < 2; mi++)
#pragma unroll
        for (int ni = 0; ni < 8; ni++)
#pragma unroll
            for (int j = 0; j < 4; j++) acc[mi][ni][j] = 0.f;

    load_chunk(0, 0);
    cpa_commit();

    for (int kc = 0; kc < 16; kc++) {
        const int cur = kc & 1;
        cpa_wait0();
        __syncthreads();
        if (kc < 15) load_chunk(cur ^ 1, (kc + 1) * 64);
        cpa_commit();

        const __half* Xc = X[cur];
        const __half* Wc = W[cur];
#pragma unroll
        for (int kk = 0; kk < 4; kk++) {
            const int kb = kk * 16;
            uint32_t a[2][4];
#pragma unroll
            for (int mi = 0; mi < 2; mi++) {
                int r = warpM * 32 + mi * 16 + gid;
                a[mi][0] = *(const uint32_t*)(Xc + r * PJ_STRIDE + kb + tig * 2);
                a[mi][1] = *(const uint32_t*)(Xc + (r + 8) * PJ_STRIDE + kb + tig * 2);
                a[mi][2] = *(const uint32_t*)(Xc + r * PJ_STRIDE + kb + tig * 2 + 8);
                a[mi][3] = *(const uint32_t*)(Xc + (r + 8) * PJ_STRIDE + kb + tig * 2 + 8);
            }
#pragma unroll
            for (int ni = 0; ni < 8; ni++) {
                int n = warpN * 64 + ni * 8 + gid;
                uint32_t b0 = *(const uint32_t*)(Wc + n * PJ_STRIDE + kb + tig * 2);
                uint32_t b1 = *(const uint32_t*)(Wc + n * PJ_STRIDE + kb + tig * 2 + 8);
#pragma unroll
                for (int mi = 0; mi < 2; mi++)
                    mma_f16(acc[mi][ni], a[mi][0], a[mi][1], a[mi][2], a[mi][3], b0, b1);
            }
        }
    }

    if (which < 2) {
        __half* outp = (which == 0) ? g_qh : g_kh;
#pragma unroll
        for (int mi = 0; mi < 2; mi++)
#pragma unroll
            for (int ni = 0; ni < 8; ni++) {
                int r0 = mbase + warpM * 32 + mi * 16 + gid;
                int c0 = warpN * 64 + ni * 8 + tig * 2;
                *(__half2*)(outp + (size_t)r0 * HS + c0) =
                    __float22half2_rn(make_float2(acc[mi][ni][0], acc[mi][ni][1]));
                *(__half2*)(outp + (size_t)(r0 + 8) * HS + c0) =
                    __float22half2_rn(make_float2(acc[mi][ni][2], acc[mi][ni][3]));
            }
    } else {
#pragma unroll
        for (int mi = 0; mi < 2; mi++)
#pragma unroll
            for (int ni = 0; ni < 8; ni++) {
                int r0 = mbase + warpM * 32 + mi * 16 + gid;
                int c0 = warpN * 64 + ni * 8 + tig * 2;
                g_vTh[(size_t)c0 * BT_TOT + r0] = __float2half_rn(acc[mi][ni][0]);
                g_vTh[(size_t)(c0 + 1) * BT_TOT + r0] = __float2half_rn(acc[mi][ni][1]);
                g_vTh[(size_t)c0 * BT_TOT + r0 + 8] = __float2half_rn(acc[mi][ni][2]);
                g_vTh[(size_t)(c0 + 1) * BT_TOT + r0 + 8] = __float2half_rn(acc[mi][ni][3]);
            }
    }
}

// ---------------------------------------------------------------------------
// Flash attention fp16: Br=128, Bs=64, 8 warps, warp owns 16 rows.
// K smem [64][136]h x2, V smem [128][72]h x2. P stays in registers (FA-2 reuse).
// ---------------------------------------------------------------------------
#define KS_STRIDE 136  // halves (68 words; 4 mod 32)
#define VS_STRIDE 72   // halves (36 words; 4 mod 32)
#define KBUF_H (64 * KS_STRIDE)     // 8704
#define VBUF_H (128 * VS_STRIDE)    // 9216
#define VOFF_H (2 * KBUF_H)         // 17408
#define FL_SMEM_H (VOFF_H + 2 * VBUF_H)  // 35840 halves = 71680 B

__device__ __forceinline__ void load_tile(uint32_t sbase, int buf, int bT, int kbase,
                                          int tid) {
    uint32_t kdst = sbase + buf * (KBUF_H * 2);
    const __half* ksrc = g_kh + (size_t)(bT + kbase) * HS;
#pragma unroll
    for (int j = 0; j < 4; j++) {
        int idx = tid + j * 256;
        int row = idx >> 4, c = idx & 15;
        cpa16(kdst + row * (KS_STRIDE * 2) + c * 16, ksrc + row * HS + c * 8);
    }
    uint32_t vdst = sbase + (VOFF_H + buf * VBUF_H) * 2;
    const __half* vsrc = g_vTh + bT + kbase;
#pragma unroll
    for (int j = 0; j < 4; j++) {
        int idx = tid + j * 256;
        int h = idx >> 3, c = idx & 7;
        cpa16(vdst + h * (VS_STRIDE * 2) + c * 16, vsrc + (size_t)h * BT_TOT + c * 8);
    }
}

__global__ __launch_bounds__(256, 1) void flash_kernel(float* __restrict__ out) {
    extern __shared__ __half smh[];
    const int tid = threadIdx.x;
    const int warp = tid >> 5, lane = tid & 31;
    const int gid = lane >> 2, tig = lane & 3;
    const int b = blockIdx.y;
    const int qt = (gridDim.x - 1) - blockIdx.x;  // longest first
    const int qbase = qt * 128;
    const int wrow = warp * 16;
    const int ktmax = 2 * qt + 1;
    const int bT = b * T_SEQ;

    __half* Ks = smh;
    __half* Vs = smh + VOFF_H;
    uint32_t sbase = (uint32_t)__cvta_generic_to_shared(smh);

    // Q fragments in registers
    uint32_t q[8][4];
    {
        const __half* Q0 = g_qh + (size_t)(bT + qbase + wrow + gid) * HS;
        const __half* Q1 = Q0 + 8 * HS;
#pragma unroll
        for (int kk = 0; kk < 8; kk++) {
            q[kk][0] = *(const uint32_t*)(Q0 + kk * 16 + tig * 2);
            q[kk][1] = *(const uint32_t*)(Q1 + kk * 16 + tig * 2);
            q[kk][2] = *(const uint32_t*)(Q0 + kk * 16 + tig * 2 + 8);
            q[kk][3] = *(const uint32_t*)(Q1 + kk * 16 + tig * 2 + 8);
        }
    }

    load_tile(sbase, 0, bT, 0, tid);
    cpa_commit();

    float o[16][4];
#pragma unroll
    for (int ni = 0; ni < 16; ni++)
#pragma unroll
        for (int j = 0; j < 4; j++) o[ni][j] = 0.f;
    float m0 = -1e30f, m1 = -1e30f, l0 = 0.f, l1 = 0.f;

    const float invs = 0.08838834764831845f;  // 1/sqrt(128)
    const int grow0 = qbase + wrow + gid;
    const int grow1 = grow0 + 8;

    for (int kt = 0; kt <= ktmax; kt++) {
        const int cur = kt & 1;
        cpa_wait0();
        __syncthreads();
        if (kt < ktmax) load_tile(sbase, cur ^ 1, bT, (kt + 1) * 64, tid);
        cpa_commit();

        const __half* Kc = Ks + cur * KBUF_H;
        const __half* Vc = Vs + cur * VBUF_H;

        // S = Q K^T (warp's 16 rows x 64 cols, k=128)
        float s[8][4];
#pragma unroll
        for (int ni = 0; ni < 8; ni++)
#pragma unroll
            for (int j = 0; j < 4; j++) s[ni][j] = 0.f;

#pragma unroll
        for (int kk = 0; kk < 8; kk++) {
            const int kb = kk * 16;
#pragma unroll
            for (int ni = 0; ni < 8; ni++) {
                const __half* kp = Kc + (ni * 8 + gid) * KS_STRIDE + kb + tig * 2;
                uint32_t b0 = *(const uint32_t*)(kp);
                uint32_t b1 = *(const uint32_t*)(kp + 8);
                mma_f16(s[ni], q[kk][0], q[kk][1], q[kk][2], q[kk][3], b0, b1);
            }
        }

        // scale + causal mask
        const int kbase = kt * 64;
        const bool dm = (kt >= 2 * qt);
#pragma unroll
        for (int ni = 0; ni < 8; ni++) {
            int c0 = kbase + ni * 8 + tig * 2;
            float v0 = s[ni][0] * invs;
            float v1 = s[ni][1] * invs;
            float v2 = s[ni][2] * invs;
            float v3 = s[ni][3] * invs;
            if (dm) {
                if (c0 > grow0) v0 = -1e30f;
                if (c0 + 1 > grow0) v1 = -1e30f;
                if (c0 > grow1) v2 = -1e30f;
                if (c0 + 1 > grow1) v3 = -1e30f;
            }
            s[ni][0] = v0;
            s[ni][1] = v1;
            s[ni][2] = v2;
            s[ni][3] = v3;
        }

        // warp-local online softmax (rows gid, gid+8)
        float mx0 = -1e30f, mx1 = -1e30f;
#pragma unroll
        for (int ni = 0; ni < 8; ni++) {
            mx0 = fmaxf(mx0, fmaxf(s[ni][0], s[ni][1]));
            mx1 = fmaxf(mx1, fmaxf(s[ni][2], s[ni][3]));
        }
        mx0 = fmaxf(mx0, __shfl_xor_sync(0xffffffffu, mx0, 1));
        mx0 = fmaxf(mx0, __shfl_xor_sync(0xffffffffu, mx0, 2));
        mx1 = fmaxf(mx1, __shfl_xor_sync(0xffffffffu, mx1, 1));
        mx1 = fmaxf(mx1, __shfl_xor_sync(0xffffffffu, mx1, 2));
        float nm0 = fmaxf(m0, mx0), nm1 = fmaxf(m1, mx1);
        float sc0 = __expf(m0 - nm0), sc1 = __expf(m1 - nm1);
        m0 = nm0;
        m1 = nm1;
        float sum0 = 0.f, sum1 = 0.f;
        // ph[ni][0] = row gid  cols (ni*8+2t, +1); ph[ni][1] = row gid+8 same cols.
        uint32_t ph[8][2];
#pragma unroll
        for (int ni = 0; ni < 8; ni++) {
            float p0 = __expf(s[ni][0] - m0);
            float p1 = __expf(s[ni][1] - m0);
            float p2 = __expf(s[ni][2] - m1);
            float p3 = __expf(s[ni][3] - m1);
            sum0 += p0 + p1;
            sum1 += p2 + p3;
            ph[ni][0] = h2u(__float22half2_rn(make_float2(p0, p1)));
            ph[ni][1] = h2u(__float22half2_rn(make_float2(p2, p3)));
        }
        sum0 += __shfl_xor_sync(0xffffffffu, sum0, 1);
        sum0 += __shfl_xor_sync(0xffffffffu, sum0, 2);
        sum1 += __shfl_xor_sync(0xffffffffu, sum1, 1);
        sum1 += __shfl_xor_sync(0xffffffffu, sum1, 2);
        l0 = l0 * sc0 + sum0;
        l1 = l1 * sc1 + sum1;

        // rescale O
#pragma unroll
        for (int ni = 0; ni < 16; ni++) {
            o[ni][0] *= sc0;
            o[ni][1] *= sc0;
            o[ni][2] *= sc1;
            o[ni][3] *= sc1;
        }

        // O += P @ V with P directly from registers:
        // A-fragment for k-block kk*16: a0=ph[2kk][0], a1=ph[2kk][1],
        // a2=ph[2kk+1][0], a3=ph[2kk+1][1]  (accumulator layout == A layout)
#pragma unroll
        for (int kk = 0; kk < 4; kk++) {
            const int kb = kk * 16;
            uint32_t a0 = ph[2 * kk][0];
            uint32_t a1 = ph[2 * kk][1];
            uint32_t a2 = ph[2 * kk + 1][0];
            uint32_t a3 = ph[2 * kk + 1][1];
#pragma unroll
            for (int ni = 0; ni < 16; ni++) {
                const __half* vp = Vc + (ni * 8 + gid) * VS_STRIDE + kb + tig * 2;
                uint32_t b0 = *(const uint32_t*)(vp);
                uint32_t b1 = *(const uint32_t*)(vp + 8);
                mma_f16(o[ni], a0, a1, a2, a3, b0, b1);
            }
        }
    }

    // epilogue
    float il0 = 1.f / l0, il1 = 1.f / l1;
    float* out0 = out + (size_t)(bT + grow0) * HS;
    float* out1 = out + (size_t)(bT + grow1) * HS;
#pragma unroll
    for (int ni = 0; ni < 16; ni++) {
        int c0 = ni * 8 + tig * 2;
        *(float2*)&out0[c0] = make_float2(o[ni][0] * il0, o[ni][1] * il0);
        *(float2*)&out1[c0] = make_float2(o[ni][2] * il1, o[ni][3] * il1);
    }
}

extern "C" void kernel_launch(void* const* d_in, const int* in_sizes, int n_in,
                              void* d_out, int out_size) {
    const float* x = (const float*)d_in[0];
    const float* Wq = (const float*)d_in[1];
    const float* Wk = (const float*)d_in[2];
    const float* Wv = (const float*)d_in[3];
    float* out = (float*)d_out;

    __half* xh_p;
    __half* wh_p;
    cudaGetSymbolAddress((void**)&xh_p, g_xh);
    cudaGetSymbolAddress((void**)&wh_p, g_wh);

    // fp32 -> fp16 conversions
    cvt_kernel<<<(BT_TOT * DM) / (256 * 8), 256>>>(x, xh_p, BT_TOT * DM);
    cvt_kernel<<<(HS * DM) / (256 * 8), 256>>>(Wq, wh_p, HS * DM);
    cvt_kernel<<<(HS * DM) / (256 * 8), 256>>>(Wk, wh_p + HS * DM, HS * DM);
    cvt_kernel<<<(HS * DM) / (256 * 8), 256>>>(Wv, wh_p + 2 * HS * DM, HS * DM);

    // projections
    const int pj_smem = 4 * PJ_BUF * (int)sizeof(__half);  // 73728
    cudaFuncSetAttribute(proj_kernel, cudaFuncAttributeMaxDynamicSharedMemorySize,
                         pj_smem);
    proj_kernel<<<dim3(128, 3), 256, pj_smem>>>();

    // flash attention
    const int fl_smem = FL_SMEM_H * (int)sizeof(__half);  // 71680
    cudaFuncSetAttribute(flash_kernel, cudaFuncAttributeMaxDynamicSharedMemorySize,
                         fl_smem);
    flash_kernel<<<dim3(32, B_BATCH), 256, fl_smem>>>(out);
}

// round 8
// speedup vs baseline: 3.2667x; 1.1507x over previous
#include <cuda_runtime.h>
#include <cuda_fp16.h>
#include <cstdint>

#define T_SEQ 4096
#define B_BATCH 4
#define DM 1024
#define HS 128
#define BT_TOT (B_BATCH * T_SEQ)
#define NQT 32  // q-tiles per batch (Br = 128)

// fp16 scratch (static device arrays; no allocations)
__device__ __half g_xh[BT_TOT * DM];
__device__ __half g_wh[3 * HS * DM];
__device__ __half g_qh[BT_TOT * HS];
__device__ __half g_kh[BT_TOT * HS];
__device__ __half g_vTh[HS * BT_TOT];  // V transposed [h][b*T+t]

// split-K partials: [b][qt][chunk] -> O' [128][HS], m/l [128]
__device__ float g_pO[B_BATCH * NQT * 2 * 128 * HS];  // 16.8 MB
__device__ float g_pm[B_BATCH * NQT * 2 * 128];
__device__ float g_pl[B_BATCH * NQT * 2 * 128];

__device__ __forceinline__ void mma_f16(float c[4],
                                        uint32_t a0, uint32_t a1, uint32_t a2, uint32_t a3,
                                        uint32_t b0, uint32_t b1) {
    asm volatile(
        "mma.sync.aligned.m16n8k16.row.col.f32.f16.f16.f32 "
        "{%0,%1,%2,%3},{%4,%5,%6,%7},{%8,%9},{%0,%1,%2,%3};\n"
        : "+f"(c[0]), "+f"(c[1]), "+f"(c[2]), "+f"(c[3])
        : "r"(a0), "r"(a1), "r"(a2), "r"(a3), "r"(b0), "r"(b1));
}

__device__ __forceinline__ void cpa16(uint32_t dst, const __half* src) {
    asm volatile("cp.async.cg.shared.global [%0], [%1], 16;\n" ::"r"(dst), "l"(src));
}
__device__ __forceinline__ void cpa_commit() { asm volatile("cp.async.commit_group;\n"); }
__device__ __forceinline__ void cpa_wait0() { asm volatile("cp.async.wait_group 0;\n"); }

__device__ __forceinline__ uint32_t h2u(__half2 h) {
    return *reinterpret_cast<uint32_t*>(&h);
}

// ---------------------------------------------------------------------------
// fp32 -> fp16 conversion (8 elems / thread)
// ---------------------------------------------------------------------------
__global__ __launch_bounds__(256) void cvt_kernel(const float* __restrict__ src,
                                                  __half* __restrict__ dst, int n) {
    int i = (blockIdx.x * 256 + threadIdx.x) * 8;
    if (i >= n) return;
    float4 a = *(const float4*)(src + i);
    float4 b = *(const float4*)(src + i + 4);
    uint4 o;
    o.x = h2u(__float22half2_rn(make_float2(a.x, a.y)));
    o.y = h2u(__float22half2_rn(make_float2(a.z, a.w)));
    o.z = h2u(__float22half2_rn(make_float2(b.x, b.y)));
    o.w = h2u(__float22half2_rn(make_float2(b.z, b.w)));
    *(uint4*)(dst + i) = o;
}

// ---------------------------------------------------------------------------
// Projection (fp16), cp.async double-buffered. Row stride 72 halves (conflict-free).
// ---------------------------------------------------------------------------
#define PJ_STRIDE 72
#define PJ_BUF (128 * PJ_STRIDE)

__global__ __launch_bounds__(256) void proj_kernel() {
    extern __shared__ __half smh[];
    __half* X[2] = {smh, smh + PJ_BUF};
    __half* W[2] = {smh + 2 * PJ_BUF, smh + 3 * PJ_BUF};
    uint32_t sbase = (uint32_t)__cvta_generic_to_shared(smh);

    const int which = blockIdx.y;
    const __half* wsrc = g_wh + (size_t)which * HS * DM;
    const int mbase = blockIdx.x * 128;
    const int tid = threadIdx.x;
    const int warp = tid >> 5, lane = tid & 31;
    const int gid = lane >> 2, tig = lane & 3;
    const int warpM = warp >> 1;
    const int warpN = warp & 1;

    auto load_chunk = [&](int buf, int k0) {
#pragma unroll
        for (int j = 0; j < 4; j++) {
            int idx = tid + j * 256;
            int row = idx >> 3, c = idx & 7;
            cpa16(sbase + buf * (PJ_BUF * 2) + row * (PJ_STRIDE * 2) + c * 16,
                  g_xh + (size_t)(mbase + row) * DM + k0 + c * 8);
            cpa16(sbase + (2 + buf) * (PJ_BUF * 2) + row * (PJ_STRIDE * 2) + c * 16,
                  wsrc + (size_t)row * DM + k0 + c * 8);
        }
    };

    float acc[2][8][4];
#pragma unroll
    for (int mi = 0; mi < 2; mi++)
#pragma unroll
        for (int ni = 0; ni < 8; ni++)
#pragma unroll
            for (int j = 0; j < 4; j++) acc[mi][ni][j] = 0.f;

    load_chunk(0, 0);
    cpa_commit();

    for (int kc = 0; kc < 16; kc++) {
        const int cur = kc & 1;
        cpa_wait0();
        __syncthreads();
        if (kc < 15) load_chunk(cur ^ 1, (kc + 1) * 64);
        cpa_commit();

        const __half* Xc = X[cur];
        const __half* Wc = W[cur];
#pragma unroll
        for (int kk = 0; kk < 4; kk++) {
            const int kb = kk * 16;
            uint32_t a[2][4];
#pragma unroll
            for (int mi = 0; mi < 2; mi++) {
                int r = warpM * 32 + mi * 16 + gid;
                a[mi][0] = *(const uint32_t*)(Xc + r * PJ_STRIDE + kb + tig * 2);
                a[mi][1] = *(const uint32_t*)(Xc + (r + 8) * PJ_STRIDE + kb + tig * 2);
                a[mi][2] = *(const uint32_t*)(Xc + r * PJ_STRIDE + kb + tig * 2 + 8);
                a[mi][3] = *(const uint32_t*)(Xc + (r + 8) * PJ_STRIDE + kb + tig * 2 + 8);
            }
#pragma unroll
            for (int ni = 0; ni < 8; ni++) {
                int n = warpN * 64 + ni * 8 + gid;
                uint32_t b0 = *(const uint32_t*)(Wc + n * PJ_STRIDE + kb + tig * 2);
                uint32_t b1 = *(const uint32_t*)(Wc + n * PJ_STRIDE + kb + tig * 2 + 8);
#pragma unroll
                for (int mi = 0; mi < 2; mi++)
                    mma_f16(acc[mi][ni], a[mi][0], a[mi][1], a[mi][2], a[mi][3], b0, b1);
            }
        }
    }

    if (which < 2) {
        __half* outp = (which == 0) ? g_qh : g_kh;
#pragma unroll
        for (int mi = 0; mi < 2; mi++)
#pragma unroll
            for (int ni = 0; ni < 8; ni++) {
                int r0 = mbase + warpM * 32 + mi * 16 + gid;
                int c0 = warpN * 64 + ni * 8 + tig * 2;
                *(__half2*)(outp + (size_t)r0 * HS + c0) =
                    __float22half2_rn(make_float2(acc[mi][ni][0], acc[mi][ni][1]));
                *(__half2*)(outp + (size_t)(r0 + 8) * HS + c0) =
                    __float22half2_rn(make_float2(acc[mi][ni][2], acc[mi][ni][3]));
            }
    } else {
#pragma unroll
        for (int mi = 0; mi < 2; mi++)
#pragma unroll
            for (int ni = 0; ni < 8; ni++) {
                int r0 = mbase + warpM * 32 + mi * 16 + gid;
                int c0 = warpN * 64 + ni * 8 + tig * 2;
                g_vTh[(size_t)c0 * BT_TOT + r0] = __float2half_rn(acc[mi][ni][0]);
                g_vTh[(size_t)(c0 + 1) * BT_TOT + r0] = __float2half_rn(acc[mi][ni][1]);
                g_vTh[(size_t)c0 * BT_TOT + r0 + 8] = __float2half_rn(acc[mi][ni][2]);
                g_vTh[(size_t)(c0 + 1) * BT_TOT + r0 + 8] = __float2half_rn(acc[mi][ni][3]);
            }
    }
}

// ---------------------------------------------------------------------------
// Flash attention, split-K: each CTA = one (q-tile, chunk) pair.
// chunk0 = k-tiles [0, qt+1), chunk1 = [qt+1, 2qt+2)  (qt+1 iters each).
// Writes unnormalized O' + (m, l) partials.
// ---------------------------------------------------------------------------
#define KS_STRIDE 136
#define VS_STRIDE 72
#define KBUF_H (64 * KS_STRIDE)
#define VBUF_H (128 * VS_STRIDE)
#define VOFF_H (2 * KBUF_H)
#define FL_SMEM_H (VOFF_H + 2 * VBUF_H)  // 35840 halves = 71680 B

__device__ __forceinline__ void load_tile(uint32_t sbase, int buf, int bT, int kbase,
                                          int tid) {
    uint32_t kdst = sbase + buf * (KBUF_H * 2);
    const __half* ksrc = g_kh + (size_t)(bT + kbase) * HS;
#pragma unroll
    for (int j = 0; j < 4; j++) {
        int idx = tid + j * 256;
        int row = idx >> 4, c = idx & 15;
        cpa16(kdst + row * (KS_STRIDE * 2) + c * 16, ksrc + row * HS + c * 8);
    }
    uint32_t vdst = sbase + (VOFF_H + buf * VBUF_H) * 2;
    const __half* vsrc = g_vTh + bT + kbase;
#pragma unroll
    for (int j = 0; j < 4; j++) {
        int idx = tid + j * 256;
        int h = idx >> 3, c = idx & 7;
        cpa16(vdst + h * (VS_STRIDE * 2) + c * 16, vsrc + (size_t)h * BT_TOT + c * 8);
    }
}

__global__ __launch_bounds__(256, 1) void flash_kernel() {
    extern __shared__ __half smh[];
    const int tid = threadIdx.x;
    const int warp = tid >> 5, lane = tid & 31;
    const int gid = lane >> 2, tig = lane & 3;
    const int b = blockIdx.y;
    const int idx = (gridDim.x - 1) - blockIdx.x;  // big qt first
    const int qt = idx >> 1;
    const int half = idx & 1;
    const int qbase = qt * 128;
    const int wrow = warp * 16;
    const int bT = b * T_SEQ;
    const int lo = half ? (qt + 1) : 0;
    const int hi = half ? (2 * qt + 2) : (qt + 1);

    __half* Ks = smh;
    __half* Vs = smh + VOFF_H;
    uint32_t sbase = (uint32_t)__cvta_generic_to_shared(smh);

    // Q fragments in registers
    uint32_t q[8][4];
    {
        const __half* Q0 = g_qh + (size_t)(bT + qbase + wrow + gid) * HS;
        const __half* Q1 = Q0 + 8 * HS;
#pragma unroll
        for (int kk = 0; kk < 8; kk++) {
            q[kk][0] = *(const uint32_t*)(Q0 + kk * 16 + tig * 2);
            q[kk][1] = *(const uint32_t*)(Q1 + kk * 16 + tig * 2);
            q[kk][2] = *(const uint32_t*)(Q0 + kk * 16 + tig * 2 + 8);
            q[kk][3] = *(const uint32_t*)(Q1 + kk * 16 + tig * 2 + 8);
        }
    }

    load_tile(sbase, 0, bT, lo * 64, tid);
    cpa_commit();

    float o[16][4];
#pragma unroll
    for (int ni = 0; ni < 16; ni++)
#pragma unroll
        for (int j = 0; j < 4; j++) o[ni][j] = 0.f;
    float m0 = -1e30f, m1 = -1e30f, l0 = 0.f, l1 = 0.f;

    const float invs = 0.08838834764831845f;  // 1/sqrt(128)
    const int grow0 = qbase + wrow + gid;
    const int grow1 = grow0 + 8;

    for (int kt = lo; kt < hi; kt++) {
        const int cur = (kt - lo) & 1;
        cpa_wait0();
        __syncthreads();
        if (kt + 1 < hi) load_tile(sbase, cur ^ 1, bT, (kt + 1) * 64, tid);
        cpa_commit();

        const __half* Kc = Ks + cur * KBUF_H;
        const __half* Vc = Vs + cur * VBUF_H;

        // S = Q K^T
        float s[8][4];
#pragma unroll
        for (int ni = 0; ni < 8; ni++)
#pragma unroll
            for (int j = 0; j < 4; j++) s[ni][j] = 0.f;

#pragma unroll
        for (int kk = 0; kk < 8; kk++) {
            const int kb = kk * 16;
#pragma unroll
            for (int ni = 0; ni < 8; ni++) {
                const __half* kp = Kc + (ni * 8 + gid) * KS_STRIDE + kb + tig * 2;
                uint32_t b0 = *(const uint32_t*)(kp);
                uint32_t b1 = *(const uint32_t*)(kp + 8);
                mma_f16(s[ni], q[kk][0], q[kk][1], q[kk][2], q[kk][3], b0, b1);
            }
        }

        // scale + causal mask (only k-tiles kt >= 2qt can cross the diagonal)
        const int kbase = kt * 64;
        const bool dm = (kt >= 2 * qt);
#pragma unroll
        for (int ni = 0; ni < 8; ni++) {
            int c0 = kbase + ni * 8 + tig * 2;
            float v0 = s[ni][0] * invs;
            float v1 = s[ni][1] * invs;
            float v2 = s[ni][2] * invs;
            float v3 = s[ni][3] * invs;
            if (dm) {
                if (c0 > grow0) v0 = -1e30f;
                if (c0 + 1 > grow0) v1 = -1e30f;
                if (c0 > grow1) v2 = -1e30f;
                if (c0 + 1 > grow1) v3 = -1e30f;
            }
            s[ni][0] = v0;
            s[ni][1] = v1;
            s[ni][2] = v2;
            s[ni][3] = v3;
        }

        // warp-local online softmax
        float mx0 = -1e30f, mx1 = -1e30f;
#pragma unroll
        for (int ni = 0; ni < 8; ni++) {
            mx0 = fmaxf(mx0, fmaxf(s[ni][0], s[ni][1]));
            mx1 = fmaxf(mx1, fmaxf(s[ni][2], s[ni][3]));
        }
        mx0 = fmaxf(mx0, __shfl_xor_sync(0xffffffffu, mx0, 1));
        mx0 = fmaxf(mx0, __shfl_xor_sync(0xffffffffu, mx0, 2));
        mx1 = fmaxf(mx1, __shfl_xor_sync(0xffffffffu, mx1, 1));
        mx1 = fmaxf(mx1, __shfl_xor_sync(0xffffffffu, mx1, 2));
        float nm0 = fmaxf(m0, mx0), nm1 = fmaxf(m1, mx1);
        float sc0 = __expf(m0 - nm0), sc1 = __expf(m1 - nm1);
        m0 = nm0;
        m1 = nm1;
        float sum0 = 0.f, sum1 = 0.f;
        uint32_t ph[8][2];  // accumulator layout == next A layout (FA-2 reuse)
#pragma unroll
        for (int ni = 0; ni < 8; ni++) {
            float p0 = __expf(s[ni][0] - m0);
            float p1 = __expf(s[ni][1] - m0);
            float p2 = __expf(s[ni][2] - m1);
            float p3 = __expf(s[ni][3] - m1);
            sum0 += p0 + p1;
            sum1 += p2 + p3;
            ph[ni][0] = h2u(__float22half2_rn(make_float2(p0, p1)));
            ph[ni][1] = h2u(__float22half2_rn(make_float2(p2, p3)));
        }
        sum0 += __shfl_xor_sync(0xffffffffu, sum0, 1);
        sum0 += __shfl_xor_sync(0xffffffffu, sum0, 2);
        sum1 += __shfl_xor_sync(0xffffffffu, sum1, 1);
        sum1 += __shfl_xor_sync(0xffffffffu, sum1, 2);
        l0 = l0 * sc0 + sum0;
        l1 = l1 * sc1 + sum1;

#pragma unroll
        for (int ni = 0; ni < 16; ni++) {
            o[ni][0] *= sc0;
            o[ni][1] *= sc0;
            o[ni][2] *= sc1;
            o[ni][3] *= sc1;
        }

        // O += P @ V, P straight from registers
#pragma unroll
        for (int kk = 0; kk < 4; kk++) {
            const int kb = kk * 16;
            uint32_t a0 = ph[2 * kk][0];
            uint32_t a1 = ph[2 * kk][1];
            uint32_t a2 = ph[2 * kk + 1][0];
            uint32_t a3 = ph[2 * kk + 1][1];
#pragma unroll
            for (int ni = 0; ni < 16; ni++) {
                const __half* vp = Vc + (ni * 8 + gid) * VS_STRIDE + kb + tig * 2;
                uint32_t b0 = *(const uint32_t*)(vp);
                uint32_t b1 = *(const uint32_t*)(vp + 8);
                mma_f16(o[ni], a0, a1, a2, a3, b0, b1);
            }
        }
    }

    // epilogue: write unnormalized partials
    const int pidx = (b * NQT + qt) * 2 + half;
    float* pO = g_pO + (size_t)pidx * 128 * HS;
    const int r0 = wrow + gid;
#pragma unroll
    for (int ni = 0; ni < 16; ni++) {
        int c0 = ni * 8 + tig * 2;
        *(float2*)&pO[r0 * HS + c0] = make_float2(o[ni][0], o[ni][1]);
        *(float2*)&pO[(r0 + 8) * HS + c0] = make_float2(o[ni][2], o[ni][3]);
    }
    if (tig == 0) {
        g_pm[pidx * 128 + r0] = m0;
        g_pl[pidx * 128 + r0] = l0;
        g_pm[pidx * 128 + r0 + 8] = m1;
        g_pl[pidx * 128 + r0 + 8] = l1;
    }
}

// ---------------------------------------------------------------------------
// Combine: out = (O0*e^{m0-m} + O1*e^{m1-m}) / (l0*e^{m0-m} + l1*e^{m1-m})
// grid (NQT, B), 256 threads; thread handles one row-half (64 cols).
// ---------------------------------------------------------------------------
__global__ __launch_bounds__(256) void combine_kernel(float* __restrict__ out) {
    const int qt = blockIdx.x, b = blockIdx.y;
    const int tid = threadIdx.x;
    const int r = tid >> 1;          // 0..127
    const int seg = (tid & 1) * 64;  // col segment

    const int p0 = (b * NQT + qt) * 2;
    const int p1 = p0 + 1;
    float m0 = g_pm[p0 * 128 + r], m1 = g_pm[p1 * 128 + r];
    float l0 = g_pl[p0 * 128 + r], l1 = g_pl[p1 * 128 + r];
    float m = fmaxf(m0, m1);
    float a0 = __expf(m0 - m), a1 = __expf(m1 - m);
    float inv = 1.f / (l0 * a0 + l1 * a1);
    a0 *= inv;
    a1 *= inv;

    const float* O0 = g_pO + ((size_t)p0 * 128 + r) * HS + seg;
    const float* O1 = g_pO + ((size_t)p1 * 128 + r) * HS + seg;
    float* dst = out + ((size_t)(b * T_SEQ + qt * 128 + r)) * HS + seg;
#pragma unroll
    for (int c = 0; c < 64; c += 4) {
        float4 v0 = *(const float4*)(O0 + c);
        float4 v1 = *(const float4*)(O1 + c);
        float4 w;
        w.x = v0.x * a0 + v1.x * a1;
        w.y = v0.y * a0 + v1.y * a1;
        w.z = v0.z * a0 + v1.z * a1;
        w.w = v0.w * a0 + v1.w * a1;
        *(float4*)(dst + c) = w;
    }
}

extern "C" void kernel_launch(void* const* d_in, const int* in_sizes, int n_in,
                              void* d_out, int out_size) {
    const float* x = (const float*)d_in[0];
    const float* Wq = (const float*)d_in[1];
    const float* Wk = (const float*)d_in[2];
    const float* Wv = (const float*)d_in[3];
    float* out = (float*)d_out;

    __half* xh_p;
    __half* wh_p;
    cudaGetSymbolAddress((void**)&xh_p, g_xh);
    cudaGetSymbolAddress((void**)&wh_p, g_wh);

    cvt_kernel<<<(BT_TOT * DM) / (256 * 8), 256>>>(x, xh_p, BT_TOT * DM);
    cvt_kernel<<<(HS * DM) / (256 * 8), 256>>>(Wq, wh_p, HS * DM);
    cvt_kernel<<<(HS * DM) / (256 * 8), 256>>>(Wk, wh_p + HS * DM, HS * DM);
    cvt_kernel<<<(HS * DM) / (256 * 8), 256>>>(Wv, wh_p + 2 * HS * DM, HS * DM);

    const int pj_smem = 4 * PJ_BUF * (int)sizeof(__half);
    cudaFuncSetAttribute(proj_kernel, cudaFuncAttributeMaxDynamicSharedMemorySize,
                         pj_smem);
    proj_kernel<<<dim3(128, 3), 256, pj_smem>>>();

    const int fl_smem = FL_SMEM_H * (int)sizeof(__half);
    cudaFuncSetAttribute(flash_kernel, cudaFuncAttributeMaxDynamicSharedMemorySize,
                         fl_smem);
    flash_kernel<<<dim3(2 * NQT, B_BATCH), 256, fl_smem>>>();

    combine_kernel<<<dim3(NQT, B_BATCH), 256>>>(out);
}

// round 16
// speedup vs baseline: 3.3310x; 1.0197x over previous
#include <cuda_runtime.h>
#include <cuda_fp16.h>
#include <cstdint>

#define T_SEQ 4096
#define B_BATCH 4
#define DM 1024
#define HS 128
#define BT_TOT (B_BATCH * T_SEQ)
#define NQT 32  // q-tiles per batch (Br = 128)

// fp16 scratch (static device arrays; no allocations)
__device__ __half g_xh[BT_TOT * DM];
__device__ __half g_wh[3 * HS * DM];
__device__ __half g_qh[BT_TOT * HS];
__device__ __half g_kh[BT_TOT * HS];
__device__ __half g_vTh[HS * BT_TOT];  // V transposed [h][b*T+t]

// split-K partials: [b][qt][chunk] -> O' [128][HS], m/l [128]
__device__ float g_pO[B_BATCH * NQT * 2 * 128 * HS];
__device__ float g_pm[B_BATCH * NQT * 2 * 128];
__device__ float g_pl[B_BATCH * NQT * 2 * 128];

__device__ __forceinline__ void mma_f16(float c[4],
                                        uint32_t a0, uint32_t a1, uint32_t a2, uint32_t a3,
                                        uint32_t b0, uint32_t b1) {
    asm volatile(
        "mma.sync.aligned.m16n8k16.row.col.f32.f16.f16.f32 "
        "{%0,%1,%2,%3},{%4,%5,%6,%7},{%8,%9},{%0,%1,%2,%3};\n"
        : "+f"(c[0]), "+f"(c[1]), "+f"(c[2]), "+f"(c[3])
        : "r"(a0), "r"(a1), "r"(a2), "r"(a3), "r"(b0), "r"(b1));
}

__device__ __forceinline__ void ldsm4(uint32_t& r0, uint32_t& r1, uint32_t& r2,
                                      uint32_t& r3, uint32_t addr) {
    asm volatile("ldmatrix.sync.aligned.m8n8.x4.shared.b16 {%0,%1,%2,%3}, [%4];"
                 : "=r"(r0), "=r"(r1), "=r"(r2), "=r"(r3)
                 : "r"(addr));
}

__device__ __forceinline__ void cpa16(uint32_t dst, const __half* src) {
    asm volatile("cp.async.cg.shared.global [%0], [%1], 16;\n" ::"r"(dst), "l"(src));
}
__device__ __forceinline__ void cpa_commit() { asm volatile("cp.async.commit_group;\n"); }
__device__ __forceinline__ void cpa_wait0() { asm volatile("cp.async.wait_group 0;\n"); }

__device__ __forceinline__ uint32_t h2u(__half2 h) {
    return *reinterpret_cast<uint32_t*>(&h);
}

// ---------------------------------------------------------------------------
// fp32 -> fp16 conversion (8 elems / thread)
// ---------------------------------------------------------------------------
__global__ __launch_bounds__(256) void cvt_kernel(const float* __restrict__ src,
                                                  __half* __restrict__ dst, int n) {
    int i = (blockIdx.x * 256 + threadIdx.x) * 8;
    if (i >= n) return;
    float4 a = *(const float4*)(src + i);
    float4 b = *(const float4*)(src + i + 4);
    uint4 o;
    o.x = h2u(__float22half2_rn(make_float2(a.x, a.y)));
    o.y = h2u(__float22half2_rn(make_float2(a.z, a.w)));
    o.z = h2u(__float22half2_rn(make_float2(b.x, b.y)));
    o.w = h2u(__float22half2_rn(make_float2(b.z, b.w)));
    *(uint4*)(dst + i) = o;
}

// ---------------------------------------------------------------------------
// Projection (fp16), cp.async double-buffered.
// grid = (3, 128): the 3 `which` CTAs of one m-tile are launch-adjacent so
// they run concurrently and share X through L2.
// ---------------------------------------------------------------------------
#define PJ_STRIDE 72
#define PJ_BUF (128 * PJ_STRIDE)

__global__ __launch_bounds__(256) void proj_kernel() {
    extern __shared__ __half smh[];
    __half* X[2] = {smh, smh + PJ_BUF};
    __half* W[2] = {smh + 2 * PJ_BUF, smh + 3 * PJ_BUF};
    uint32_t sbase = (uint32_t)__cvta_generic_to_shared(smh);

    const int which = blockIdx.x;
    const __half* wsrc = g_wh + (size_t)which * HS * DM;
    const int mbase = blockIdx.y * 128;
    const int tid = threadIdx.x;
    const int warp = tid >> 5, lane = tid & 31;
    const int gid = lane >> 2, tig = lane & 3;
    const int warpM = warp >> 1;
    const int warpN = warp & 1;

    auto load_chunk = [&](int buf, int k0) {
#pragma unroll
        for (int j = 0; j < 4; j++) {
            int idx = tid + j * 256;
            int row = idx >> 3, c = idx & 7;
            cpa16(sbase + buf * (PJ_BUF * 2) + row * (PJ_STRIDE * 2) + c * 16,
                  g_xh + (size_t)(mbase + row) * DM + k0 + c * 8);
            cpa16(sbase + (2 + buf) * (PJ_BUF * 2) + row * (PJ_STRIDE * 2) + c * 16,
                  wsrc + (size_t)row * DM + k0 + c * 8);
        }
    };

    float acc[2][8][4];
#pragma unroll
    for (int mi = 0; mi < 2; mi++)
#pragma unroll
        for (int ni = 0; ni < 8; ni++)
#pragma unroll
            for (int j = 0; j < 4; j++) acc[mi][ni][j] = 0.f;

    load_chunk(0, 0);
    cpa_commit();

    for (int kc = 0; kc < 16; kc++) {
        const int cur = kc & 1;
        cpa_wait0();
        __syncthreads();
        if (kc < 15) load_chunk(cur ^ 1, (kc + 1) * 64);
        cpa_commit();

        const __half* Xc = X[cur];
        const __half* Wc = W[cur];
#pragma unroll
        for (int kk = 0; kk < 4; kk++) {
            const int kb = kk * 16;
            uint32_t a[2][4];
#pragma unroll
            for (int mi = 0; mi < 2; mi++) {
                int r = warpM * 32 + mi * 16 + gid;
                a[mi][0] = *(const uint32_t*)(Xc + r * PJ_STRIDE + kb + tig * 2);
                a[mi][1] = *(const uint32_t*)(Xc + (r + 8) * PJ_STRIDE + kb + tig * 2);
                a[mi][2] = *(const uint32_t*)(Xc + r * PJ_STRIDE + kb + tig * 2 + 8);
                a[mi][3] = *(const uint32_t*)(Xc + (r + 8) * PJ_STRIDE + kb + tig * 2 + 8);
            }
#pragma unroll
            for (int ni = 0; ni < 8; ni++) {
                int n = warpN * 64 + ni * 8 + gid;
                uint32_t b0 = *(const uint32_t*)(Wc + n * PJ_STRIDE + kb + tig * 2);
                uint32_t b1 = *(const uint32_t*)(Wc + n * PJ_STRIDE + kb + tig * 2 + 8);
#pragma unroll
                for (int mi = 0; mi < 2; mi++)
                    mma_f16(acc[mi][ni], a[mi][0], a[mi][1], a[mi][2], a[mi][3], b0, b1);
            }
        }
    }

    if (which < 2) {
        __half* outp = (which == 0) ? g_qh : g_kh;
#pragma unroll
        for (int mi = 0; mi < 2; mi++)
#pragma unroll
            for (int ni = 0; ni < 8; ni++) {
                int r0 = mbase + warpM * 32 + mi * 16 + gid;
                int c0 = warpN * 64 + ni * 8 + tig * 2;
                *(__half2*)(outp + (size_t)r0 * HS + c0) =
                    __float22half2_rn(make_float2(acc[mi][ni][0], acc[mi][ni][1]));
                *(__half2*)(outp + (size_t)(r0 + 8) * HS + c0) =
                    __float22half2_rn(make_float2(acc[mi][ni][2], acc[mi][ni][3]));
            }
    } else {
#pragma unroll
        for (int mi = 0; mi < 2; mi++)
#pragma unroll
            for (int ni = 0; ni < 8; ni++) {
                int r0 = mbase + warpM * 32 + mi * 16 + gid;
                int c0 = warpN * 64 + ni * 8 + tig * 2;
                g_vTh[(size_t)c0 * BT_TOT + r0] = __float2half_rn(acc[mi][ni][0]);
                g_vTh[(size_t)(c0 + 1) * BT_TOT + r0] = __float2half_rn(acc[mi][ni][1]);
                g_vTh[(size_t)c0 * BT_TOT + r0 + 8] = __float2half_rn(acc[mi][ni][2]);
                g_vTh[(size_t)(c0 + 1) * BT_TOT + r0 + 8] = __float2half_rn(acc[mi][ni][3]);
            }
    }
}

// ---------------------------------------------------------------------------
// Flash attention, split-K, ldmatrix fragment loads.
// ---------------------------------------------------------------------------
#define KS_STRIDE 136
#define VS_STRIDE 72
#define KBUF_H (64 * KS_STRIDE)
#define VBUF_H (128 * VS_STRIDE)
#define VOFF_H (2 * KBUF_H)
#define FL_SMEM_H (VOFF_H + 2 * VBUF_H)  // 35840 halves = 71680 B

__device__ __forceinline__ void load_tile(uint32_t sbase, int buf, int bT, int kbase,
                                          int tid) {
    uint32_t kdst = sbase + buf * (KBUF_H * 2);
    const __half* ksrc = g_kh + (size_t)(bT + kbase) * HS;
#pragma unroll
    for (int j = 0; j < 4; j++) {
        int idx = tid + j * 256;
        int row = idx >> 4, c = idx & 15;
        cpa16(kdst + row * (KS_STRIDE * 2) + c * 16, ksrc + row * HS + c * 8);
    }
    uint32_t vdst = sbase + (VOFF_H + buf * VBUF_H) * 2;
    const __half* vsrc = g_vTh + bT + kbase;
#pragma unroll
    for (int j = 0; j < 4; j++) {
        int idx = tid + j * 256;
        int h = idx >> 3, c = idx & 7;
        cpa16(vdst + h * (VS_STRIDE * 2) + c * 16, vsrc + (size_t)h * BT_TOT + c * 8);
    }
}

__global__ __launch_bounds__(256, 1) void flash_kernel() {
    extern __shared__ __half smh[];
    const int tid = threadIdx.x;
    const int warp = tid >> 5, lane = tid & 31;
    const int gid = lane >> 2, tig = lane & 3;
    const int b = blockIdx.y;
    const int idx = (gridDim.x - 1) - blockIdx.x;  // big qt first
    const int qt = idx >> 1;
    const int half = idx & 1;
    const int qbase = qt * 128;
    const int wrow = warp * 16;
    const int bT = b * T_SEQ;
    const int lo = half ? (qt + 1) : 0;
    const int hi = half ? (2 * qt + 2) : (qt + 1);

    uint32_t sbase = (uint32_t)__cvta_generic_to_shared(smh);

    // ldmatrix per-lane address offsets (bytes):
    // lquad = lane>>3 selects (n-half, k-half); lr = lane&7 is the row.
    const int lquad = lane >> 3, lr = lane & 7;
    const uint32_t lane_k =
        (uint32_t)(((lquad >> 1) * 8 + lr) * (KS_STRIDE * 2) + (lquad & 1) * 16);
    const uint32_t lane_v =
        (uint32_t)(((lquad >> 1) * 8 + lr) * (VS_STRIDE * 2) + (lquad & 1) * 16);

    // Q fragments in registers
    uint32_t q[8][4];
    {
        const __half* Q0 = g_qh + (size_t)(bT + qbase + wrow + gid) * HS;
        const __half* Q1 = Q0 + 8 * HS;
#pragma unroll
        for (int kk = 0; kk < 8; kk++) {
            q[kk][0] = *(const uint32_t*)(Q0 + kk * 16 + tig * 2);
            q[kk][1] = *(const uint32_t*)(Q1 + kk * 16 + tig * 2);
            q[kk][2] = *(const uint32_t*)(Q0 + kk * 16 + tig * 2 + 8);
            q[kk][3] = *(const uint32_t*)(Q1 + kk * 16 + tig * 2 + 8);
        }
    }

    load_tile(sbase, 0, bT, lo * 64, tid);
    cpa_commit();

    float o[16][4];
#pragma unroll
    for (int ni = 0; ni < 16; ni++)
#pragma unroll
        for (int j = 0; j < 4; j++) o[ni][j] = 0.f;
    float m0 = -1e30f, m1 = -1e30f, l0 = 0.f, l1 = 0.f;

    const float invs = 0.08838834764831845f;  // 1/sqrt(128)
    const int grow0 = qbase + wrow + gid;
    const int grow1 = grow0 + 8;

    for (int kt = lo; kt < hi; kt++) {
        const int cur = (kt - lo) & 1;
        cpa_wait0();
        __syncthreads();
        if (kt + 1 < hi) load_tile(sbase, cur ^ 1, bT, (kt + 1) * 64, tid);
        cpa_commit();

        const uint32_t kc_s = sbase + cur * (KBUF_H * 2) + lane_k;
        const uint32_t vc_s = sbase + (VOFF_H + cur * VBUF_H) * 2 + lane_v;

        // S = Q K^T : ldmatrix.x4 covers (2 n-tiles, 1 k-step) per issue
        float s[8][4];
#pragma unroll
        for (int ni = 0; ni < 8; ni++)
#pragma unroll
            for (int j = 0; j < 4; j++) s[ni][j] = 0.f;

#pragma unroll
        for (int kk = 0; kk < 8; kk++) {
#pragma unroll
            for (int nip = 0; nip < 4; nip++) {
                uint32_t r0, r1, r2, r3;
                ldsm4(r0, r1, r2, r3,
                      kc_s + nip * (16 * KS_STRIDE * 2) + kk * 32);
                mma_f16(s[2 * nip], q[kk][0], q[kk][1], q[kk][2], q[kk][3], r0, r1);
                mma_f16(s[2 * nip + 1], q[kk][0], q[kk][1], q[kk][2], q[kk][3], r2, r3);
            }
        }

        // scale + causal mask
        const int kbase = kt * 64;
        const bool dm = (kt >= 2 * qt);
#pragma unroll
        for (int ni = 0; ni < 8; ni++) {
            int c0 = kbase + ni * 8 + tig * 2;
            float v0 = s[ni][0] * invs;
            float v1 = s[ni][1] * invs;
            float v2 = s[ni][2] * invs;
            float v3 = s[ni][3] * invs;
            if (dm) {
                if (c0 > grow0) v0 = -1e30f;
                if (c0 + 1 > grow0) v1 = -1e30f;
                if (c0 > grow1) v2 = -1e30f;
                if (c0 + 1 > grow1) v3 = -1e30f;
            }
            s[ni][0] = v0;
            s[ni][1] = v1;
            s[ni][2] = v2;
            s[ni][3] = v3;
        }

        // warp-local online softmax
        float mx0 = -1e30f, mx1 = -1e30f;
#pragma unroll
        for (int ni = 0; ni < 8; ni++) {
            mx0 = fmaxf(mx0, fmaxf(s[ni][0], s[ni][1]));
            mx1 = fmaxf(mx1, fmaxf(s[ni][2], s[ni][3]));
        }
        mx0 = fmaxf(mx0, __shfl_xor_sync(0xffffffffu, mx0, 1));
        mx0 = fmaxf(mx0, __shfl_xor_sync(0xffffffffu, mx0, 2));
        mx1 = fmaxf(mx1, __shfl_xor_sync(0xffffffffu, mx1, 1));
        mx1 = fmaxf(mx1, __shfl_xor_sync(0xffffffffu, mx1, 2));
        float nm0 = fmaxf(m0, mx0), nm1 = fmaxf(m1, mx1);
        float sc0 = __expf(m0 - nm0), sc1 = __expf(m1 - nm1);
        m0 = nm0;
        m1 = nm1;
        float sum0 = 0.f, sum1 = 0.f;
        uint32_t ph[8][2];  // accumulator layout == next A layout (FA-2 reuse)
#pragma unroll
        for (int ni = 0; ni < 8; ni++) {
            float p0 = __expf(s[ni][0] - m0);
            float p1 = __expf(s[ni][1] - m0);
            float p2 = __expf(s[ni][2] - m1);
            float p3 = __expf(s[ni][3] - m1);
            sum0 += p0 + p1;
            sum1 += p2 + p3;
            ph[ni][0] = h2u(__float22half2_rn(make_float2(p0, p1)));
            ph[ni][1] = h2u(__float22half2_rn(make_float2(p2, p3)));
        }
        sum0 += __shfl_xor_sync(0xffffffffu, sum0, 1);
        sum0 += __shfl_xor_sync(0xffffffffu, sum0, 2);
        sum1 += __shfl_xor_sync(0xffffffffu, sum1, 1);
        sum1 += __shfl_xor_sync(0xffffffffu, sum1, 2);
        l0 = l0 * sc0 + sum0;
        l1 = l1 * sc1 + sum1;

#pragma unroll
        for (int ni = 0; ni < 16; ni++) {
            o[ni][0] *= sc0;
            o[ni][1] *= sc0;
            o[ni][2] *= sc1;
            o[ni][3] *= sc1;
        }

        // O += P @ V, P straight from registers, V via ldmatrix.x4
#pragma unroll
        for (int kk = 0; kk < 4; kk++) {
            uint32_t a0 = ph[2 * kk][0];
            uint32_t a1 = ph[2 * kk][1];
            uint32_t a2 = ph[2 * kk + 1][0];
            uint32_t a3 = ph[2 * kk + 1][1];
#pragma unroll
            for (int nip = 0; nip < 8; nip++) {
                uint32_t r0, r1, r2, r3;
                ldsm4(r0, r1, r2, r3,
                      vc_s + nip * (16 * VS_STRIDE * 2) + kk * 32);
                mma_f16(o[2 * nip], a0, a1, a2, a3, r0, r1);
                mma_f16(o[2 * nip + 1], a0, a1, a2, a3, r2, r3);
            }
        }
    }

    // epilogue: write unnormalized partials
    const int pidx = (b * NQT + qt) * 2 + half;
    float* pO = g_pO + (size_t)pidx * 128 * HS;
    const int r0 = wrow + gid;
#pragma unroll
    for (int ni = 0; ni < 16; ni++) {
        int c0 = ni * 8 + tig * 2;
        *(float2*)&pO[r0 * HS + c0] = make_float2(o[ni][0], o[ni][1]);
        *(float2*)&pO[(r0 + 8) * HS + c0] = make_float2(o[ni][2], o[ni][3]);
    }
    if (tig == 0) {
        g_pm[pidx * 128 + r0] = m0;
        g_pl[pidx * 128 + r0] = l0;
        g_pm[pidx * 128 + r0 + 8] = m1;
        g_pl[pidx * 128 + r0 + 8] = l1;
    }
}

// ---------------------------------------------------------------------------
// Combine partials
// ---------------------------------------------------------------------------
__global__ __launch_bounds__(256) void combine_kernel(float* __restrict__ out) {
    const int qt = blockIdx.x, b = blockIdx.y;
    const int tid = threadIdx.x;
    const int r = tid >> 1;
    const int seg = (tid & 1) * 64;

    const int p0 = (b * NQT + qt) * 2;
    const int p1 = p0 + 1;
    float m0 = g_pm[p0 * 128 + r], m1 = g_pm[p1 * 128 + r];
    float l0 = g_pl[p0 * 128 + r], l1 = g_pl[p1 * 128 + r];
    float m = fmaxf(m0, m1);
    float a0 = __expf(m0 - m), a1 = __expf(m1 - m);
    float inv = 1.f / (l0 * a0 + l1 * a1);
    a0 *= inv;
    a1 *= inv;

    const float* O0 = g_pO + ((size_t)p0 * 128 + r) * HS + seg;
    const float* O1 = g_pO + ((size_t)p1 * 128 + r) * HS + seg;
    float* dst = out + ((size_t)(b * T_SEQ + qt * 128 + r)) * HS + seg;
#pragma unroll
    for (int c = 0; c < 64; c += 4) {
        float4 v0 = *(const float4*)(O0 + c);
        float4 v1 = *(const float4*)(O1 + c);
        float4 w;
        w.x = v0.x * a0 + v1.x * a1;
        w.y = v0.y * a0 + v1.y * a1;
        w.z = v0.z * a0 + v1.z * a1;
        w.w = v0.w * a0 + v1.w * a1;
        *(float4*)(dst + c) = w;
    }
}

extern "C" void kernel_launch(void* const* d_in, const int* in_sizes, int n_in,
                              void* d_out, int out_size) {
    const float* x = (const float*)d_in[0];
    const float* Wq = (const float*)d_in[1];
    const float* Wk = (const float*)d_in[2];
    const float* Wv = (const float*)d_in[3];
    float* out = (float*)d_out;

    __half* xh_p;
    __half* wh_p;
    cudaGetSymbolAddress((void**)&xh_p, g_xh);
    cudaGetSymbolAddress((void**)&wh_p, g_wh);

    cvt_kernel<<<(BT_TOT * DM) / (256 * 8), 256>>>(x, xh_p, BT_TOT * DM);
    cvt_kernel<<<(HS * DM) / (256 * 8), 256>>>(Wq, wh_p, HS * DM);
    cvt_kernel<<<(HS * DM) / (256 * 8), 256>>>(Wk, wh_p + HS * DM, HS * DM);
    cvt_kernel<<<(HS * DM) / (256 * 8), 256>>>(Wv, wh_p + 2 * HS * DM, HS * DM);

    const int pj_smem = 4 * PJ_BUF * (int)sizeof(__half);
    cudaFuncSetAttribute(proj_kernel, cudaFuncAttributeMaxDynamicSharedMemorySize,
                         pj_smem);
    proj_kernel<<<dim3(3, 128), 256, pj_smem>>>();

    const int fl_smem = FL_SMEM_H * (int)sizeof(__half);
    cudaFuncSetAttribute(flash_kernel, cudaFuncAttributeMaxDynamicSharedMemorySize,
                         fl_smem);
    flash_kernel<<<dim3(2 * NQT, B_BATCH), 256, fl_smem>>>();

    combine_kernel<<<dim3(NQT, B_BATCH), 256>>>(out);
}